// round 1
// baseline (speedup 1.0000x reference)
#include <cuda_runtime.h>
#include <cuda_bf16.h>

// Problem: B = 2,000,000 rows, M=3, L=16.
// inputs: d_in[0]=x (B*3 f32), d_in[1]=phis (48 f32), d_in[2]=interval (3 f32),
//         d_in[3]=weight (48 f32). out = concat(y[B], weight[48]).

__device__ float g_phi[48];
__device__ float g_A[48];
__device__ float g_B[48];
__device__ float g_C[48];
__device__ float g_iv[3];

// One-shot precompute: A = 0.5*cos(phi)*w[s], B = 0.5*sin(phi)*w[s], C = 0.5*w[s]
// with s = 3*m + l (segment id). Also copies weight to the output tail.
__global__ void precomp_kernel(const float* __restrict__ phis,
                               const float* __restrict__ interval,
                               const float* __restrict__ weight,
                               float* __restrict__ out_w, int copy_w)
{
    int i = threadIdx.x;
    if (i < 48) {
        float p = phis[i];
        int m = i >> 4, l = i & 15;
        int s = m * 3 + l;                 // segment id (max 21)
        float w = weight[s];
        float sp, cp;
        sincosf(p, &sp, &cp);              // precise; runs once
        g_phi[i] = p;
        g_A[i] = 0.5f * cp * w;
        g_B[i] = 0.5f * sp * w;
        g_C[i] = 0.5f * w;
        if (copy_w) out_w[i] = weight[i];
    }
    if (i < 3) g_iv[i] = interval[i];
}

// Main kernel: 4 rows per thread via float4 loads.
__global__ __launch_bounds__(256)
void bspline_kernel(const float4* __restrict__ x4, float4* __restrict__ y4, int n4)
{
    __shared__ float sphi[48], sA[48], sB[48], sC[48], siv[3];
    int t = threadIdx.x;
    if (t < 48) { sphi[t] = g_phi[t]; sA[t] = g_A[t]; sB[t] = g_B[t]; sC[t] = g_C[t]; }
    if (t < 3)  siv[t] = g_iv[t];
    __syncthreads();

    int tid = blockIdx.x * blockDim.x + t;
    if (tid >= n4) return;

    float4 v0 = x4[3 * tid + 0];
    float4 v1 = x4[3 * tid + 1];
    float4 v2 = x4[3 * tid + 2];
    // row e has x[e][m]; rows are contiguous triples.
    float x0[4] = {v0.x, v0.w, v1.z, v2.y};
    float x1[4] = {v0.y, v1.x, v1.w, v2.z};
    float x2[4] = {v0.z, v1.y, v2.x, v2.w};

    float a0[4], b0[4], a1[4], b1[4], a2[4], b2[4], cc[4];
    unsigned msk1[4], msk2[4];
#pragma unroll
    for (int e = 0; e < 4; e++) {
        a0[e] = b0[e] = a1[e] = b1[e] = a2[e] = b2[e] = cc[e] = 0.0f;
        msk1[e] = msk2[e] = 0u;
    }

    // ---- m = 2 pass: winner iff cond2 ----
    {
        float iv = siv[2];
#pragma unroll
        for (int l = 0; l < 16; l++) {
            float p = sphi[32 + l], Al = sA[32 + l], Bl = sB[32 + l], Cl = sC[32 + l];
#pragma unroll
            for (int e = 0; e < 4; e++) {
                float d = x2[e] - p;
                bool c = (d > -iv) && (d <= iv);
                msk2[e] |= ((unsigned)c) << l;
                if (c) { a2[e] += Al; b2[e] += Bl; cc[e] += Cl; }
            }
        }
    }
    // ---- m = 1 pass: winner iff cond1 && !cond2[l-3] ----
    {
        float iv = siv[1];
#pragma unroll
        for (int l = 0; l < 16; l++) {
            float p = sphi[16 + l], Al = sA[16 + l], Bl = sB[16 + l], Cl = sC[16 + l];
#pragma unroll
            for (int e = 0; e < 4; e++) {
                float d = x1[e] - p;
                bool c = (d > -iv) && (d <= iv);
                msk1[e] |= ((unsigned)c) << l;
                bool win = c;
                if (l >= 3) win = win && !((msk2[e] >> (l - 3)) & 1u);
                if (win) { a1[e] += Al; b1[e] += Bl; cc[e] += Cl; }
            }
        }
    }
    // ---- m = 0 pass: winner iff cond0 && !cond1[l-3] && !cond2[l-6] ----
    {
        float iv = siv[0];
#pragma unroll
        for (int l = 0; l < 16; l++) {
            float p = sphi[l], Al = sA[l], Bl = sB[l], Cl = sC[l];
#pragma unroll
            for (int e = 0; e < 4; e++) {
                float d = x0[e] - p;
                bool c = (d > -iv) && (d <= iv);
                bool win = c;
                if (l >= 3) win = win && !((msk1[e] >> (l - 3)) & 1u);
                if (l >= 6) win = win && !((msk2[e] >> (l - 6)) & 1u);
                if (win) { a0[e] += Al; b0[e] += Bl; cc[e] += Cl; }
            }
        }
    }

    float out[4];
#pragma unroll
    for (int e = 0; e < 4; e++) {
        float s0, c0, s1, c1, s2, c2;
        __sincosf(x0[e], &s0, &c0);
        __sincosf(x1[e], &s1, &c1);
        __sincosf(x2[e], &s2, &c2);
        float r = cc[e];
        r = fmaf(c0, a0[e], r); r = fmaf(s0, b0[e], r);
        r = fmaf(c1, a1[e], r); r = fmaf(s1, b1[e], r);
        r = fmaf(c2, a2[e], r); r = fmaf(s2, b2[e], r);
        out[e] = r;
    }
    y4[tid] = make_float4(out[0], out[1], out[2], out[3]);
}

// Scalar tail (only used if B % 4 != 0; B=2e6 so normally unused).
__global__ void tail_kernel(const float* __restrict__ x, float* __restrict__ y,
                            int start, int B)
{
    int i = start + blockIdx.x * blockDim.x + threadIdx.x;
    if (i >= B) return;
    float xm[3] = {x[3 * i], x[3 * i + 1], x[3 * i + 2]};
    bool cond[3][16];
    float r = 0.0f;
    for (int m = 0; m < 3; m++) {
        float iv = g_iv[m];
        for (int l = 0; l < 16; l++) {
            float d = xm[m] - g_phi[m * 16 + l];
            cond[m][l] = (d > -iv) && (d <= iv);
        }
    }
    for (int m = 0; m < 3; m++) {
        float sm, cm;
        sincosf(xm[m], &sm, &cm);
        for (int l = 0; l < 16; l++) {
            bool win = cond[m][l];
            if (m <= 1 && l >= 3) win = win && !cond[m + 1][l - 3];
            if (m == 0 && l >= 6) win = win && !cond[2][l - 6];
            if (win) {
                int i48 = m * 16 + l;
                r += cm * g_A[i48] + sm * g_B[i48] + g_C[i48];
            }
        }
    }
    y[i] = r;
}

extern "C" void kernel_launch(void* const* d_in, const int* in_sizes, int n_in,
                              void* d_out, int out_size)
{
    const float* x        = (const float*)d_in[0];
    const float* phis     = (const float*)d_in[1];
    const float* interval = (const float*)d_in[2];
    const float* weight   = (const float*)d_in[3];
    float* out = (float*)d_out;

    int B = in_sizes[0] / 3;
    int copy_w = (out_size >= B + 48) ? 1 : 0;

    precomp_kernel<<<1, 64>>>(phis, interval, weight, out + B, copy_w);

    int n4 = B >> 2;
    if (n4 > 0) {
        int blocks = (n4 + 255) / 256;
        bspline_kernel<<<blocks, 256>>>((const float4*)x, (float4*)out, n4);
    }
    int rem = B - (n4 << 2);
    if (rem > 0) {
        tail_kernel<<<1, 128>>>(x, out, n4 << 2, B);
    }
}

// round 2
// speedup vs baseline: 1.8067x; 1.8067x over previous
#include <cuda_runtime.h>
#include <cuda_bf16.h>

// B = 2,000,000 rows, M=3, L=16.
// inputs: d_in[0]=x (B*3 f32), d_in[1]=phis (48 f32), d_in[2]=interval (3 f32),
//         d_in[3]=weight (48 f32). out = concat(y[B], weight[48]).
//
// Strategy: per coordinate m, the 16-bit condition mask cond(m,l) depends only on
// which of 33 intervals (delimited by exact flip thresholds of fl(x-phi)<=+-iv)
// x_m falls in. Precompute a 33^3-entry table of the fully-resolved weighted sums
// (A_m, B_m, C) so the main kernel is: 3 binary searches + 1 table lookup +
// 3 sincos + 6 FMA per row.

#define NK 33
#define NT0 (NK * NK * NK) // 35937

__device__ float    g_bp[3][32];     // sorted breakpoints per m
__device__ unsigned g_cm[3][NK];     // cond mask per (m, interval)
__device__ float4   g_abc[48];       // per (m,l): (0.5cos(phi)w, 0.5sin(phi)w, 0.5w, 0)
__device__ float4   g_T0[NT0 * 2];   // [2*idx]=(A0,B0,A1,B1), [2*idx+1]=(A2,B2,C,0)

// ---- ordered-float key helpers (monotone bijection float <-> uint) ----
__device__ __forceinline__ unsigned f2key(float f) {
    unsigned u = __float_as_uint(f);
    return (u & 0x80000000u) ? ~u : (u | 0x80000000u);
}
__device__ __forceinline__ float key2f(unsigned k) {
    return (k & 0x80000000u) ? __uint_as_float(k ^ 0x80000000u)
                             : __uint_as_float(~k);
}

// P1: exact thresholds (bisection over float bit-space), sort breakpoints,
// interval cond masks, abc coefficients, weight tail copy. Single block.
__global__ void p1_kernel(const float* __restrict__ phis,
                          const float* __restrict__ interval,
                          const float* __restrict__ weight,
                          float* __restrict__ out_w, int copy_w)
{
    __shared__ float s_th[3][32];
    __shared__ float s_bp[3][32];
    __shared__ float s_tlo[3][16], s_thi[3][16];
    int i = threadIdx.x;

    // Phase A: exact flip thresholds. t = max{x : fl(x - phi) <= c}.
    if (i < 96) {
        int m = i / 32, j = i % 32;
        int l = j >> 1, hi = j & 1;
        float phi = phis[m * 16 + l];
        float iv  = interval[m];
        float c   = hi ? iv : -iv;
        unsigned lo = f2key(-1e30f), hk = f2key(1e30f);
        // invariant: P(lo) true, P(hk) false; fl(x-phi) monotone in x
        while (hk - lo > 1u) {
            unsigned mid = lo + ((hk - lo) >> 1u);
            float x = key2f(mid);
            if (x - phi <= c) lo = mid; else hk = mid;
        }
        float t = key2f(lo);
        s_th[m][j] = t;
        if (hi) s_thi[m][l] = t; else s_tlo[m][l] = t;
    }
    __syncthreads();

    // Phase B: rank sort (32 elems per m, ties by index)
    if (i < 96) {
        int m = i / 32, j = i % 32;
        float v = s_th[m][j];
        int r = 0;
        for (int q = 0; q < 32; q++) {
            float u = s_th[m][q];
            r += (u < v) || (u == v && q < j);
        }
        s_bp[m][r] = v;
    }
    __syncthreads();

    // Phase C: cond mask per interval k = (bp[k-1], bp[k]]; representative x = bp[k].
    // k==32 (x > max bp) -> empty mask; k==0 is empty automatically.
    if (i < 99) {
        int m = i / 33, k = i % 33;
        unsigned mask = 0;
        if (k < 32) {
            float x = s_bp[m][k];
            #pragma unroll
            for (int l = 0; l < 16; l++)
                if (x > s_tlo[m][l] && x <= s_thi[m][l]) mask |= (1u << l);
        }
        g_cm[m][k] = mask;
    }
    if (i < 96) { int m = i / 32, j = i % 32; g_bp[m][j] = s_bp[m][j]; }

    // Phase D: abc coefficients (precise sincos, runs once) + weight passthrough
    if (i < 48) {
        int m = i >> 4, l = i & 15;
        float w = weight[m * 3 + l];   // segment id s = 3m + l
        float sp, cp;
        sincosf(phis[i], &sp, &cp);
        g_abc[i] = make_float4(0.5f * cp * w, 0.5f * sp * w, 0.5f * w, 0.0f);
        if (copy_w) out_w[i] = weight[i];
    }
}

// P2: fill the 33^3 win-sum table.
__global__ void p2_kernel()
{
    int idx = blockIdx.x * blockDim.x + threadIdx.x;
    if (idx >= NT0) return;
    int k0 = idx / (NK * NK);
    int r  = idx % (NK * NK);
    int k1 = r / NK, k2 = r % NK;
    unsigned m0 = g_cm[0][k0], m1 = g_cm[1][k1], m2 = g_cm[2][k2];
    unsigned w2 = m2;
    unsigned w1 = m1 & ~(m2 << 3);
    unsigned w0 = m0 & ~(m1 << 3) & ~(m2 << 6);
    float A0=0, B0=0, A1=0, B1=0, A2=0, B2=0, C=0;
    #pragma unroll
    for (int l = 0; l < 16; l++) {
        if ((w0 >> l) & 1u) { float4 t = g_abc[l];      A0 += t.x; B0 += t.y; C += t.z; }
        if ((w1 >> l) & 1u) { float4 t = g_abc[16 + l]; A1 += t.x; B1 += t.y; C += t.z; }
        if ((w2 >> l) & 1u) { float4 t = g_abc[32 + l]; A2 += t.x; B2 += t.y; C += t.z; }
    }
    g_T0[2 * idx]     = make_float4(A0, B0, A1, B1);
    g_T0[2 * idx + 1] = make_float4(A2, B2, C, 0.0f);
}

// Main: 4 rows/thread via float4. Per row: 3 branchless lower_bounds over smem
// (32 floats = 32 banks -> conflict-free), one 32B table read, 3 sincos, 6 FMA.
__global__ __launch_bounds__(256)
void bspline_kernel(const float4* __restrict__ x4, float4* __restrict__ y4, int n4)
{
    __shared__ float sbp[3][32];
    int t = threadIdx.x;
    if (t < 96) sbp[t / 32][t % 32] = g_bp[t / 32][t % 32];
    __syncthreads();

    int tid = blockIdx.x * blockDim.x + t;
    if (tid >= n4) return;

    float4 v0 = x4[3 * tid + 0];
    float4 v1 = x4[3 * tid + 1];
    float4 v2 = x4[3 * tid + 2];
    float X0[4] = {v0.x, v0.w, v1.z, v2.y};
    float X1[4] = {v0.y, v1.x, v1.w, v2.z};
    float X2[4] = {v0.z, v1.y, v2.x, v2.w};

    int K0[4], K1[4], K2[4];
    #pragma unroll
    for (int m = 0; m < 3; m++) {
        const float* b = sbp[m];
        #pragma unroll
        for (int e = 0; e < 4; e++) {
            float x = (m == 0) ? X0[e] : (m == 1) ? X1[e] : X2[e];
            int it = 0;
            if (b[15]     < x) it  = 16;
            if (b[it + 7] < x) it += 8;
            if (b[it + 3] < x) it += 4;
            if (b[it + 1] < x) it += 2;
            if (b[it]     < x) it += 1;
            if (b[it]     < x) it += 1;   // count == 32 case
            if (m == 0) K0[e] = it; else if (m == 1) K1[e] = it; else K2[e] = it;
        }
    }

    float res[4];
    #pragma unroll
    for (int e = 0; e < 4; e++) {
        int idx = (K0[e] * NK + K1[e]) * NK + K2[e];
        float4 ta = __ldg(&g_T0[2 * idx]);
        float4 tb = __ldg(&g_T0[2 * idx + 1]);
        float s0, c0, s1, c1, s2, c2;
        __sincosf(X0[e], &s0, &c0);
        __sincosf(X1[e], &s1, &c1);
        __sincosf(X2[e], &s2, &c2);
        float r = tb.z;
        r = fmaf(c0, ta.x, r); r = fmaf(s0, ta.y, r);
        r = fmaf(c1, ta.z, r); r = fmaf(s1, ta.w, r);
        r = fmaf(c2, tb.x, r); r = fmaf(s2, tb.y, r);
        res[e] = r;
    }
    y4[tid] = make_float4(res[0], res[1], res[2], res[3]);
}

// Scalar tail (B % 4 != 0; unused for B = 2e6 but kept for generality).
__global__ void tail_kernel(const float* __restrict__ x, float* __restrict__ y,
                            int start, int B)
{
    int i = start + blockIdx.x * blockDim.x + threadIdx.x;
    if (i >= B) return;
    int K[3];
    float xs[3];
    for (int m = 0; m < 3; m++) {
        float xv = x[3 * i + m];
        xs[m] = xv;
        const float* b = g_bp[m];
        int it = 0;
        if (b[15]     < xv) it  = 16;
        if (b[it + 7] < xv) it += 8;
        if (b[it + 3] < xv) it += 4;
        if (b[it + 1] < xv) it += 2;
        if (b[it]     < xv) it += 1;
        if (b[it]     < xv) it += 1;
        K[m] = it;
    }
    int idx = (K[0] * NK + K[1]) * NK + K[2];
    float4 ta = g_T0[2 * idx];
    float4 tb = g_T0[2 * idx + 1];
    float s0, c0, s1, c1, s2, c2;
    __sincosf(xs[0], &s0, &c0);
    __sincosf(xs[1], &s1, &c1);
    __sincosf(xs[2], &s2, &c2);
    float r = tb.z;
    r = fmaf(c0, ta.x, r); r = fmaf(s0, ta.y, r);
    r = fmaf(c1, ta.z, r); r = fmaf(s1, ta.w, r);
    r = fmaf(c2, tb.x, r); r = fmaf(s2, tb.y, r);
    y[i] = r;
}

extern "C" void kernel_launch(void* const* d_in, const int* in_sizes, int n_in,
                              void* d_out, int out_size)
{
    const float* x        = (const float*)d_in[0];
    const float* phis     = (const float*)d_in[1];
    const float* interval = (const float*)d_in[2];
    const float* weight   = (const float*)d_in[3];
    float* out = (float*)d_out;

    int B = in_sizes[0] / 3;
    int copy_w = (out_size >= B + 48) ? 1 : 0;

    p1_kernel<<<1, 128>>>(phis, interval, weight, out + B, copy_w);
    p2_kernel<<<(NT0 + 255) / 256, 256>>>();

    int n4 = B >> 2;
    if (n4 > 0) {
        int blocks = (n4 + 255) / 256;
        bspline_kernel<<<blocks, 256>>>((const float4*)x, (float4*)out, n4);
    }
    int rem = B - (n4 << 2);
    if (rem > 0) {
        tail_kernel<<<1, 128>>>(x, out, n4 << 2, B);
    }
}